// round 15
// baseline (speedup 1.0000x reference)
#include <cuda_runtime.h>
#include <cuda_bf16.h>
#include <cstdint>
#include <cstddef>

#define B_   32
#define T_   512
#define KIN  1024
#define H_   1024
#define G_   4096
#define M_   (B_*T_)
#define NBLK 128
#define NTHR 1024

__device__ float    g_xproj[(size_t)M_ * G_];
__device__ unsigned g_hh[2][B_*512];     // h hi, bf16x2 per k-pair
__device__ unsigned g_hl[2][B_*512];     // h lo
__device__ unsigned g_arr[8*32];         // setup barrier
__device__ unsigned g_arrA[8*32];        // group A tags
__device__ unsigned g_arrB[8*32];        // group B tags

typedef unsigned long long u64;

__device__ __forceinline__ void fma2(u64 &d, u64 a, u64 b){
    asm("fma.rn.f32x2 %0, %1, %2, %0;" : "+l"(d) : "l"(a), "l"(b));
}
__device__ __forceinline__ u64 pack2(float lo, float hi){
    u64 r; asm("mov.b64 %0, {%1,%2};" : "=l"(r) : "f"(lo), "f"(hi)); return r;
}
__device__ __forceinline__ float2 unpack2(u64 v){
    float2 f; asm("mov.b64 {%0,%1}, %2;" : "=f"(f.x), "=f"(f.y) : "l"(v)); return f;
}
__device__ __forceinline__ uint32_t smem_to_u32(const void* p) {
    uint32_t a;
    asm("{ .reg .u64 t; cvta.to.shared.u64 t, %1; cvt.u32.u64 %0, t; }"
        : "=r"(a) : "l"(p));
    return a;
}
__device__ __forceinline__ void ldsm_x4(uint32_t* r, uint32_t addr){
    asm volatile("ldmatrix.sync.aligned.m8n8.x4.shared.b16 {%0,%1,%2,%3}, [%4];"
        : "=r"(r[0]),"=r"(r[1]),"=r"(r[2]),"=r"(r[3]) : "r"(addr));
}
__device__ __forceinline__ void ldsm_x2(uint32_t* r, uint32_t addr){
    asm volatile("ldmatrix.sync.aligned.m8n8.x2.shared.b16 {%0,%1}, [%2];"
        : "=r"(r[0]),"=r"(r[1]) : "r"(addr));
}
__device__ __forceinline__ void mma16816(float* c, const uint32_t* a,
                                         const uint32_t* b){
    asm volatile("mma.sync.aligned.m16n8k16.row.col.f32.bf16.bf16.f32 "
        "{%0,%1,%2,%3}, {%4,%5,%6,%7}, {%8,%9}, {%0,%1,%2,%3};"
        : "+f"(c[0]),"+f"(c[1]),"+f"(c[2]),"+f"(c[3])
        : "r"(a[0]),"r"(a[1]),"r"(a[2]),"r"(a[3]),"r"(b[0]),"r"(b[1]));
}

__device__ __forceinline__ void grid_sync(int jb, unsigned e)
{
    __syncthreads();
    if (threadIdx.x == 0) {
        __threadfence();
        atomicAdd(&g_arr[(jb & 7) * 32], 1u);
        unsigned tgt = 16u * e;
        volatile unsigned* a = g_arr;
        for (;;) {
            unsigned v0=a[0],v1=a[32],v2=a[64],v3=a[96];
            unsigned v4=a[128],v5=a[160],v6=a[192],v7=a[224];
            if (v0>=tgt&&v1>=tgt&&v2>=tgt&&v3>=tgt&&
                v4>=tgt&&v5>=tgt&&v6>=tgt&&v7>=tgt) break;
        }
        __threadfence();
    }
    __syncthreads();
}

// arrive on own group's counter (optional) then wait next group's tag
__device__ __forceinline__ void arr_wait(unsigned* own, bool doArr,
                                         unsigned* nxt, unsigned tgt, int jb)
{
    __syncthreads();
    if (threadIdx.x == 0) {
        __threadfence();
        if (doArr) atomicAdd(&own[(jb & 7) * 32], 1u);
        volatile unsigned* a = nxt;
        for (;;) {
            unsigned v0=a[0],v1=a[32],v2=a[64],v3=a[96];
            unsigned v4=a[128],v5=a[160],v6=a[192],v7=a[224];
            if (v0>=tgt&&v1>=tgt&&v2>=tgt&&v3>=tgt&&
                v4>=tgt&&v5>=tgt&&v6>=tgt&&v7>=tgt) break;
        }
        __threadfence();
    }
    __syncthreads();
}

// scan smem byte offsets
#define HPITCH    1032                    // bf16 per row
#define HGB       66048                   // per-group h buffer (hi+lo)
#define HLOFF     33024                   // lo offset within group buffer
#define OFF_PD    132096                  // [16 ks][32 m][20] float
#define OFF_SP    173056                  // [32 m][20] float
#define OFF_SXP   175616                  // [32 b][32 n] float
#define SMEM_BYTES (175616 + 4096 + 512)
// xproj alias: As2 u64[16][258], Bst float[16][132]
#define XP_AP      258
#define XP_BST_OFF (16*XP_AP*2)

extern __shared__ __align__(16) char smemc[];

__global__ void __launch_bounds__(NTHR, 1) lstm_fused(
    const float* __restrict__ A,
    const float* __restrict__ h0,
    const float* __restrict__ c0,
    const float* __restrict__ Wih,
    const float* __restrict__ bih,
    const float* __restrict__ Whh,
    const float* __restrict__ bhh,
    float* __restrict__ out)
{
    const int tid  = threadIdx.x;
    const int jb   = blockIdx.x;
    const int wid  = tid >> 5;
    const int lane = tid & 31;

    if (jb == 0 && tid < 8) {
        g_arr[tid*32] = 0u; g_arrA[tid*32] = 0u; g_arrB[tid*32] = 0u;
        __threadfence();
    }
    unsigned epoch = 0;

    // ===== Phase A: xproj (proven 1024-thr fp32 f32x2), 256m x 128n =====
    {
        float* smemf = (float*)smemc;
        u64*   As2 = (u64*)smemf;
        float* Bst = smemf + XP_BST_OFF;
        const int tx   = tid & 31;
        const int ty   = tid >> 5;
        const int arow = tid >> 2;
        const int akq  = (tid & 3) * 4;

        for (int i6 = 0; i6 < 16; i6++) {
            int tt = jb*16 + i6;
            int m0 = (tt >> 5) * 256, n0 = (tt & 31) * 128;
            u64 acc[8][2];
            #pragma unroll
            for (int i = 0; i < 8; i++) { acc[i][0]=0ULL; acc[i][1]=0ULL; }
            const float* Ap = A + (size_t)(m0 + arow)*KIN + akq;
            const float* Wp = Wih + (size_t)(n0 + (arow & 127))*KIN + akq;

            for (int kc = 0; kc < KIN; kc += 16) {
                float4 av = *(const float4*)(Ap + kc);
                float4 wv;
                if (tid < 512) wv = *(const float4*)(Wp + kc);
                As2[(akq+0)*XP_AP + arow] = pack2(av.x, av.x);
                As2[(akq+1)*XP_AP + arow] = pack2(av.y, av.y);
                As2[(akq+2)*XP_AP + arow] = pack2(av.z, av.z);
                As2[(akq+3)*XP_AP + arow] = pack2(av.w, av.w);
                if (tid < 512) {
                    Bst[(akq+0)*132 + arow] = wv.x;
                    Bst[(akq+1)*132 + arow] = wv.y;
                    Bst[(akq+2)*132 + arow] = wv.z;
                    Bst[(akq+3)*132 + arow] = wv.w;
                }
                __syncthreads();
                #pragma unroll
                for (int k = 0; k < 16; k++) {
                    const ulonglong2* ap =
                        (const ulonglong2*)&As2[k*XP_AP + ty*8];
                    ulonglong2 bv = *(const ulonglong2*)&Bst[k*132 + tx*4];
                    #pragma unroll
                    for (int mh = 0; mh < 4; mh++) {
                        ulonglong2 a2 = ap[mh];
                        fma2(acc[2*mh  ][0], a2.x, bv.x);
                        fma2(acc[2*mh  ][1], a2.x, bv.y);
                        fma2(acc[2*mh+1][0], a2.y, bv.x);
                        fma2(acc[2*mh+1][1], a2.y, bv.y);
                    }
                }
                __syncthreads();
            }
            float4 bn = *(const float4*)(bih + n0 + tx*4);
            #pragma unroll
            for (int i = 0; i < 8; i++) {
                float2 v0 = unpack2(acc[i][0]), v1 = unpack2(acc[i][1]);
                float4 o;
                o.x = v0.x + bn.x; o.y = v0.y + bn.y;
                o.z = v1.x + bn.z; o.w = v1.y + bn.w;
                *(float4*)(g_xproj + (size_t)(m0 + ty*8 + i)*G_
                           + n0 + tx*4) = o;
            }
        }
    }
    grid_sync(jb, ++epoch);

    // ===== Setup: W -> bf16 hi/lo smem; h0 -> bf16 hi/lo global =====
    char* sm = smemc;
    const uint32_t smu = smem_to_u32(sm);
    __nv_bfloat16* sHhi = (__nv_bfloat16*)sm;            // [32][HPITCH]
    __nv_bfloat16* sHlo = (__nv_bfloat16*)(sm + HGB);    // [32][HPITCH]
    float* pd  = (float*)(sm + OFF_PD);
    float* sp  = (float*)(sm + OFF_SP);
    float* sxp = (float*)(sm + OFF_SXP);

    for (int i = tid; i < 32*1024; i += NTHR) {
        int n = i >> 10, k = i & 1023;
        int wr = (n >> 3)*H_ + jb*8 + (n & 7);
        float v = Whh[(size_t)wr*KIN + k];
        __nv_bfloat16 hb = __float2bfloat16(v);
        sHhi[n*HPITCH + k] = hb;
        sHlo[n*HPITCH + k] = __float2bfloat16(v - __bfloat162float(hb));
    }
    if (tid < 128) {
        int u = jb*128 + tid;
        int b = u >> 9, kp = u & 511;
        float v0 = h0[b*KIN + 2*kp], v1 = h0[b*KIN + 2*kp + 1];
        __nv_bfloat16 a0 = __float2bfloat16(v0), a1 = __float2bfloat16(v1);
        __nv_bfloat162 hp; hp.x = a0; hp.y = a1;
        __nv_bfloat162 lp;
        lp.x = __float2bfloat16(v0 - __bfloat162float(a0));
        lp.y = __float2bfloat16(v1 - __bfloat162float(a1));
        g_hh[0][u] = *(unsigned*)&hp;
        g_hl[0][u] = *(unsigned*)&lp;
    }
    __syncthreads();

    // A-fragments (W): warp = (mt, ks of 16); 4 ktiles x hi/lo = 32 regs
    const int mt = wid & 1, ks = wid >> 1;
    uint32_t aHi[4][4], aLo[4][4];
    {
        int g = lane >> 3, r = lane & 7;
        int row = mt*16 + r + (g & 1)*8;
        int kof = (g >> 1)*8;
        #pragma unroll
        for (int kt = 0; kt < 4; kt++) {
            uint32_t boff = (uint32_t)(row*HPITCH + ks*64 + kt*16 + kof)*2;
            ldsm_x4(aHi[kt], smu + boff);
            ldsm_x4(aLo[kt], smu + HGB + boff);
        }
    }
    __syncthreads();
    grid_sync(jb, ++epoch);   // h0 conversion visible everywhere

    // cell state: tid<64 owns (ub 0..15, jjp) for BOTH groups
    const int ub = tid >> 2, jjp = tid & 3;
    const int j0 = jb*8 + 2*jjp;
    float cs[2][2] = {{0.f,0.f},{0.f,0.f}};
    if (tid < 64) {
        cs[0][0] = c0[ub*H_ + j0];       cs[0][1] = c0[ub*H_ + j0 + 1];
        cs[1][0] = c0[(16+ub)*H_ + j0];  cs[1][1] = c0[(16+ub)*H_ + j0 + 1];
    }

    const int bl_r = lane & 7;
    const int bl_k = (lane >> 3) & 1;
    const size_t OFF_H = (size_t)B_*T_*H_;
    const size_t OFF_C = OFF_H + (size_t)B_*H_;

    // ===== Scan: two batch groups, arrive-early / wait-late =====
    for (int t = 0; t < T_; t++) {
        #pragma unroll
        for (int g = 0; g < 2; g++) {
            const int b0 = g*16;
            char* hsb = sm + g*HGB;          // this group's h buffer

            // stage group h (hi+lo) + sxp(g==0)
            {
                const uint4* ph = (const uint4*)g_hh[t & 1];
                const uint4* pl = (const uint4*)g_hl[t & 1];
                #pragma unroll
                for (int it = 0; it < 2; it++) {
                    int e = tid + NTHR*it;          // 0..2047
                    int r = e >> 7, kq = e & 127;
                    *(uint4*)(hsb + (r*HPITCH + kq*8)*2) = ph[(b0+r)*128 + kq];
                    *(uint4*)(hsb + HLOFF + (r*HPITCH + kq*8)*2) =
                        pl[(b0+r)*128 + kq];
                }
                if (g == 0) {
                    int b = tid >> 5, n = tid & 31;
                    int col = (n >> 3)*H_ + jb*8 + (n & 7);
                    sxp[tid] = g_xproj[((size_t)b*T_ + t)*G_ + col] + bhh[col];
                }
            }
            __syncthreads();

            // MMA: 4 ktiles x 2 btiles x 3 splits
            {
                float acc[2][4];
                acc[0][0]=acc[0][1]=acc[0][2]=acc[0][3]=0.f;
                acc[1][0]=acc[1][1]=acc[1][2]=acc[1][3]=0.f;
                const uint32_t hbase = smu + (uint32_t)(g*HGB);
                #pragma unroll
                for (int kt = 0; kt < 4; kt++) {
                    uint32_t k0 = (uint32_t)(ks*64 + kt*16 + bl_k*8);
                    #pragma unroll
                    for (int bt = 0; bt < 2; bt++) {
                        uint32_t bo = ((uint32_t)(bt*8 + bl_r)*HPITCH + k0)*2;
                        uint32_t bhi[2], blo[2];
                        ldsm_x2(bhi, hbase + bo);
                        ldsm_x2(blo, hbase + HLOFF + bo);
                        mma16816(acc[bt], aHi[kt], bhi);
                        mma16816(acc[bt], aHi[kt], blo);
                        mma16816(acc[bt], aLo[kt], bhi);
                    }
                }
                int row = mt*16 + (lane >> 2);
                int bc  = (lane & 3)*2;
                #pragma unroll
                for (int bt = 0; bt < 2; bt++) {
                    float* p0 = pd + (ks*32 + row)*20 + bt*8 + bc;
                    p0[0] = acc[bt][0]; p0[1] = acc[bt][1];
                    float* p1 = pd + (ks*32 + row + 8)*20 + bt*8 + bc;
                    p1[0] = acc[bt][2]; p1[1] = acc[bt][3];
                }
            }
            __syncthreads();

            // reduce 16 k-splits: 128 threads, 2 interleaved chains
            if (tid < 128) {
                int m = tid >> 2, q = tid & 3;
                const float* base = pd + m*20 + q*4;
                float4 s0 = base[0] ? *(const float4*)base
                                    : *(const float4*)base; // keep simple
                s0 = *(const float4*)base;
                float4 s1 = *(const float4*)(base + 640);
                #pragma unroll
                for (int s16 = 2; s16 < 16; s16 += 2) {
                    float4 v0 = *(const float4*)(base + s16*640);
                    float4 v1 = *(const float4*)(base + (s16+1)*640);
                    s0.x += v0.x; s0.y += v0.y; s0.z += v0.z; s0.w += v0.w;
                    s1.x += v1.x; s1.y += v1.y; s1.z += v1.z; s1.w += v1.w;
                }
                s0.x += s1.x; s0.y += s1.y; s0.z += s1.z; s0.w += s1.w;
                *(float4*)(sp + m*20 + q*4) = s0;
            }
            __syncthreads();

            // epilogue: tid<64, (ub, jjp), batches b0+ub
            if (tid < 64) {
                float pre0[4], pre1[4];
                #pragma unroll
                for (int gg = 0; gg < 4; gg++) {
                    int n0 = gg*8 + 2*jjp;
                    int b  = b0 + ub;
                    pre0[gg] = sp[n0*20 + ub]
                             + sxp[b*32 + n0];
                    pre1[gg] = sp[(n0+1)*20 + ub]
                             + sxp[b*32 + n0 + 1];
                }
                float i0 = 1.f/(1.f+__expf(-pre0[0]));
                float f0 = 1.f/(1.f+__expf(-pre0[1]));
                float o0 = 1.f/(1.f+__expf(-pre0[2]));
                float q0 = tanhf(pre0[3]);
                float i1 = 1.f/(1.f+__expf(-pre1[0]));
                float f1 = 1.f/(1.f+__expf(-pre1[1]));
                float o1 = 1.f/(1.f+__expf(-pre1[2]));
                float q1 = tanhf(pre1[3]);
                cs[g][0] = cs[g][0]*f0 + i0*q0;
                cs[g][1] = cs[g][1]*f1 + i1*q1;
                float hn0 = o0 * tanhf(cs[g][0]);
                float hn1 = o1 * tanhf(cs[g][1]);

                int b = b0 + ub;
                out[((size_t)b*T_ + t)*H_ + j0]     = hn0;
                out[((size_t)b*T_ + t)*H_ + j0 + 1] = hn1;
                if (t == T_ - 1) {
                    out[OFF_H + (size_t)b*H_ + j0]     = hn0;
                    out[OFF_H + (size_t)b*H_ + j0 + 1] = hn1;
                    out[OFF_C + (size_t)b*H_ + j0]     = cs[g][0];
                    out[OFF_C + (size_t)b*H_ + j0 + 1] = cs[g][1];
                }
                __nv_bfloat16 a0 = __float2bfloat16(hn0);
                __nv_bfloat16 a1 = __float2bfloat16(hn1);
                __nv_bfloat162 hp; hp.x = a0; hp.y = a1;
                __nv_bfloat162 lp;
                lp.x = __float2bfloat16(hn0 - __bfloat162float(a0));
                lp.y = __float2bfloat16(hn1 - __bfloat162float(a1));
                g_hh[(t+1)&1][b*512 + jb*4 + jjp] = *(unsigned*)&hp;
                g_hl[(t+1)&1][b*512 + jb*4 + jjp] = *(unsigned*)&lp;
            }

            // publish this group's h(t+1); wait the tag the NEXT phase needs
            if (g == 0) {
                // next phase: B at step t (tag count 16*t)
                arr_wait(g_arrA, t + 1 < T_, g_arrB, 16u*(unsigned)t, jb);
            } else if (t + 1 < T_) {
                // next phase: A at step t+1 (tag count 16*(t+1))
                arr_wait(g_arrB, true, g_arrA, 16u*(unsigned)(t+1), jb);
            }
        }
    }
}

extern "C" void kernel_launch(void* const* d_in, const int* in_sizes, int n_in,
                              void* d_out, int out_size)
{
    (void)in_sizes; (void)n_in; (void)out_size;
    const float* inputs = (const float*)d_in[0];
    const float* h0     = (const float*)d_in[1];
    const float* c0     = (const float*)d_in[2];
    const float* Wih    = (const float*)d_in[3];
    const float* bih    = (const float*)d_in[4];
    const float* Whh    = (const float*)d_in[5];
    const float* bhh    = (const float*)d_in[6];
    float* out = (float*)d_out;

    cudaFuncSetAttribute(lstm_fused,
                         cudaFuncAttributeMaxDynamicSharedMemorySize,
                         SMEM_BYTES);

    lstm_fused<<<NBLK, NTHR, SMEM_BYTES>>>(
        inputs, h0, c0, Wih, bih, Whh, bhh, out);
}

// round 16
// speedup vs baseline: 1.6450x; 1.6450x over previous
#include <cuda_runtime.h>
#include <cuda_bf16.h>
#include <cstdint>
#include <cstddef>

#define B_   32
#define T_   512
#define KIN  1024
#define H_   1024
#define G_   4096
#define M_   (B_*T_)
#define NBLK 128
#define NTHR 1024

__device__ float    g_xproj[(size_t)M_ * G_];
__device__ unsigned g_hh[2][B_*512];     // h hi, bf16x2 per k-pair
__device__ unsigned g_hl[2][B_*512];     // h lo
__device__ unsigned g_arr[8*32];         // tree barrier
__device__ unsigned g_xh[(size_t)M_*512];   // inputs hi (bf16x2)
__device__ unsigned g_xl[(size_t)M_*512];   // inputs lo
__device__ unsigned g_wh[(size_t)G_*512];   // Wih hi
__device__ unsigned g_wl[(size_t)G_*512];   // Wih lo

typedef unsigned long long u64;

__device__ __forceinline__ uint32_t smem_to_u32(const void* p) {
    uint32_t a;
    asm("{ .reg .u64 t; cvta.to.shared.u64 t, %1; cvt.u32.u64 %0, t; }"
        : "=r"(a) : "l"(p));
    return a;
}
__device__ __forceinline__ void ldsm_x4(uint32_t* r, uint32_t addr){
    asm volatile("ldmatrix.sync.aligned.m8n8.x4.shared.b16 {%0,%1,%2,%3}, [%4];"
        : "=r"(r[0]),"=r"(r[1]),"=r"(r[2]),"=r"(r[3]) : "r"(addr));
}
__device__ __forceinline__ void ldsm_x2(uint32_t* r, uint32_t addr){
    asm volatile("ldmatrix.sync.aligned.m8n8.x2.shared.b16 {%0,%1}, [%2];"
        : "=r"(r[0]),"=r"(r[1]) : "r"(addr));
}
__device__ __forceinline__ void mma16816(float* c, const uint32_t* a,
                                         const uint32_t* b){
    asm volatile("mma.sync.aligned.m16n8k16.row.col.f32.bf16.bf16.f32 "
        "{%0,%1,%2,%3}, {%4,%5,%6,%7}, {%8,%9}, {%0,%1,%2,%3};"
        : "+f"(c[0]),"+f"(c[1]),"+f"(c[2]),"+f"(c[3])
        : "r"(a[0]),"r"(a[1]),"r"(a[2]),"r"(a[3]),"r"(b[0]),"r"(b[1]));
}
// split one float4 into bf16x2 hi/lo words
__device__ __forceinline__ void cvt_split(float4 v, unsigned* h, unsigned* l){
    __nv_bfloat16 h0 = __float2bfloat16(v.x), h1 = __float2bfloat16(v.y);
    __nv_bfloat16 h2 = __float2bfloat16(v.z), h3 = __float2bfloat16(v.w);
    __nv_bfloat162 a, b, c, d;
    a.x = h0; a.y = h1; b.x = h2; b.y = h3;
    c.x = __float2bfloat16(v.x - __bfloat162float(h0));
    c.y = __float2bfloat16(v.y - __bfloat162float(h1));
    d.x = __float2bfloat16(v.z - __bfloat162float(h2));
    d.y = __float2bfloat16(v.w - __bfloat162float(h3));
    h[0] = *(unsigned*)&a; h[1] = *(unsigned*)&b;
    l[0] = *(unsigned*)&c; l[1] = *(unsigned*)&d;
}

__device__ __forceinline__ void grid_sync(int jb, unsigned e)
{
    __syncthreads();
    if (threadIdx.x == 0) {
        __threadfence();
        atomicAdd(&g_arr[(jb & 7) * 32], 1u);
        unsigned tgt = 16u * e;
        volatile unsigned* a = g_arr;
        for (;;) {
            unsigned v0=a[0],v1=a[32],v2=a[64],v3=a[96];
            unsigned v4=a[128],v5=a[160],v6=a[192],v7=a[224];
            if (v0>=tgt&&v1>=tgt&&v2>=tgt&&v3>=tgt&&
                v4>=tgt&&v5>=tgt&&v6>=tgt&&v7>=tgt) break;
        }
        __threadfence();
    }
    __syncthreads();
}

// scan smem byte offsets (round-14 layout, unchanged)
#define HPITCH    1032
#define OFF_HHI   0
#define OFF_HLO   66048
#define OFF_PD    132096                  // [16 ks][32 m][36] float
#define OFF_SP    205824                  // [32 m][40] float
#define OFF_SXP   210944                  // [32 b][32 n] float
#define SMEM_BYTES (210944 + 4096)
// xproj GEMM aliases (bytes): A/W tiles 128 rows x 72 bf16 (144 B pitch)
#define XG_AH 0
#define XG_AL 18432
#define XG_WH 36864
#define XG_WL 55296

extern __shared__ __align__(16) char smemc[];

__global__ void __launch_bounds__(NTHR, 1) lstm_fused(
    const float* __restrict__ A,
    const float* __restrict__ h0,
    const float* __restrict__ c0,
    const float* __restrict__ Wih,
    const float* __restrict__ bih,
    const float* __restrict__ Whh,
    const float* __restrict__ bhh,
    float* __restrict__ out)
{
    const int tid  = threadIdx.x;
    const int jb   = blockIdx.x;
    const int wid  = tid >> 5;
    const int lane = tid & 31;

    if (jb == 0 && tid < 8) { g_arr[tid*32] = 0u; __threadfence(); }
    unsigned epoch = 0;

    char* sm = smemc;
    const uint32_t smu = smem_to_u32(sm);

    // ===== Phase A0: convert inputs & Wih to bf16 hi/lo =====
    {
        const float4* src = (const float4*)A;
        for (int i = jb*NTHR + tid; i < M_*256; i += NBLK*NTHR) {
            unsigned h[2], l[2];
            cvt_split(src[i], h, l);
            g_xh[2*i] = h[0]; g_xh[2*i+1] = h[1];
            g_xl[2*i] = l[0]; g_xl[2*i+1] = l[1];
        }
        const float4* ws = (const float4*)Wih;
        for (int i = jb*NTHR + tid; i < G_*256; i += NBLK*NTHR) {
            unsigned h[2], l[2];
            cvt_split(ws[i], h, l);
            g_wh[2*i] = h[0]; g_wh[2*i+1] = h[1];
            g_wl[2*i] = l[0]; g_wl[2*i+1] = l[1];
        }
    }
    grid_sync(jb, ++epoch);

    // ===== Phase A1: xproj GEMM (bf16 3-split MMA) =====
    // block owns m-strip jb*128; 32 n-tiles of 128. Warp = 32m x 16n.
    {
        const int mw = wid & 3, nw = wid >> 2;
        const int r8 = tid >> 3, q8 = tid & 7;      // staging coords
        const int lg = lane >> 3, lr = lane & 7;
        const int kofA = (lg >> 1) * 8;
        const int bl_r = lane & 7, bl_k = (lane >> 3) & 1;
        const int m0 = jb * 128;

        for (int i6 = 0; i6 < 32; i6++) {
            int n0 = i6 * 128;
            float acc[2][2][4];
            #pragma unroll
            for (int a0 = 0; a0 < 2; a0++)
                #pragma unroll
                for (int a1 = 0; a1 < 2; a1++)
                    acc[a0][a1][0]=acc[a0][a1][1]=acc[a0][a1][2]=acc[a0][a1][3]=0.f;

            for (int kc = 0; kc < KIN; kc += 64) {
                // stage 4 x (128 x 64 bf16) tiles
                {
                    int si = r8*144 + q8*16;        // byte offset in tile
                    size_t gx = (size_t)(m0 + r8)*128 + (kc >> 3) + q8;
                    size_t gw = (size_t)(n0 + r8)*128 + (kc >> 3) + q8;
                    *(uint4*)(sm + XG_AH + si) = ((const uint4*)g_xh)[gx];
                    *(uint4*)(sm + XG_AL + si) = ((const uint4*)g_xl)[gx];
                    *(uint4*)(sm + XG_WH + si) = ((const uint4*)g_wh)[gw];
                    *(uint4*)(sm + XG_WL + si) = ((const uint4*)g_wl)[gw];
                }
                __syncthreads();

                #pragma unroll
                for (int kk = 0; kk < 4; kk++) {
                    uint32_t aH[2][4], aL[2][4];
                    #pragma unroll
                    for (int ms = 0; ms < 2; ms++) {
                        int row = mw*32 + ms*16 + lr + (lg & 1)*8;
                        uint32_t off = (uint32_t)(row*72 + kk*16 + kofA)*2;
                        ldsm_x4(aH[ms], smu + XG_AH + off);
                        ldsm_x4(aL[ms], smu + XG_AL + off);
                    }
                    uint32_t bH[2][2], bL[2][2];
                    #pragma unroll
                    for (int ns = 0; ns < 2; ns++) {
                        int nr = nw*16 + ns*8 + bl_r;
                        uint32_t off = (uint32_t)(nr*72 + kk*16 + bl_k*8)*2;
                        ldsm_x2(bH[ns], smu + XG_WH + off);
                        ldsm_x2(bL[ns], smu + XG_WL + off);
                    }
                    #pragma unroll
                    for (int ms = 0; ms < 2; ms++)
                        #pragma unroll
                        for (int ns = 0; ns < 2; ns++) {
                            mma16816(acc[ms][ns], aH[ms], bH[ns]);
                            mma16816(acc[ms][ns], aH[ms], bL[ns]);
                            mma16816(acc[ms][ns], aL[ms], bH[ns]);
                        }
                }
                __syncthreads();
            }

            // epilogue: add bih, write g_xproj
            int r0 = lane >> 2, c2 = (lane & 3)*2;
            #pragma unroll
            for (int ns = 0; ns < 2; ns++) {
                int nc = n0 + nw*16 + ns*8 + c2;
                float b0 = bih[nc], b1 = bih[nc+1];
                #pragma unroll
                for (int ms = 0; ms < 2; ms++) {
                    int mr = m0 + mw*32 + ms*16 + r0;
                    float2 v;
                    v.x = acc[ms][ns][0] + b0; v.y = acc[ms][ns][1] + b1;
                    *(float2*)(g_xproj + (size_t)mr*G_ + nc) = v;
                    v.x = acc[ms][ns][2] + b0; v.y = acc[ms][ns][3] + b1;
                    *(float2*)(g_xproj + (size_t)(mr+8)*G_ + nc) = v;
                }
            }
        }
    }
    grid_sync(jb, ++epoch);

    // ===== Setup: Whh -> bf16 hi/lo smem; h0 -> bf16 hi/lo global =====
    __nv_bfloat16* sHhi = (__nv_bfloat16*)(sm + OFF_HHI);
    __nv_bfloat16* sHlo = (__nv_bfloat16*)(sm + OFF_HLO);
    float* pd  = (float*)(sm + OFF_PD);
    float* sp  = (float*)(sm + OFF_SP);
    float* sxp = (float*)(sm + OFF_SXP);

    for (int i = tid; i < 32*1024; i += NTHR) {
        int n = i >> 10, k = i & 1023;
        int wr = (n >> 3)*H_ + jb*8 + (n & 7);
        float v = Whh[(size_t)wr*KIN + k];
        __nv_bfloat16 hb = __float2bfloat16(v);
        sHhi[n*HPITCH + k] = hb;
        sHlo[n*HPITCH + k] = __float2bfloat16(v - __bfloat162float(hb));
    }
    if (tid < 128) {
        int u = jb*128 + tid;
        int b = u >> 9, kp = u & 511;
        float v0 = h0[b*KIN + 2*kp], v1 = h0[b*KIN + 2*kp + 1];
        __nv_bfloat16 a0 = __float2bfloat16(v0), a1 = __float2bfloat16(v1);
        __nv_bfloat162 hp; hp.x = a0; hp.y = a1;
        __nv_bfloat162 lp;
        lp.x = __float2bfloat16(v0 - __bfloat162float(a0));
        lp.y = __float2bfloat16(v1 - __bfloat162float(a1));
        g_hh[0][u] = *(unsigned*)&hp;
        g_hl[0][u] = *(unsigned*)&lp;
    }
    __syncthreads();

    // A-fragments (Whh): warp = (mt, ks of 16); 4 ktiles x hi/lo
    const int mt = wid & 1, ks = wid >> 1;
    uint32_t aHi[4][4], aLo[4][4];
    {
        int g = lane >> 3, r = lane & 7;
        int row = mt*16 + r + (g & 1)*8;
        int kof = (g >> 1)*8;
        #pragma unroll
        for (int kt = 0; kt < 4; kt++) {
            uint32_t boff = (uint32_t)(row*HPITCH + ks*64 + kt*16 + kof)*2;
            ldsm_x4(aHi[kt], smu + OFF_HHI + boff);
            ldsm_x4(aLo[kt], smu + OFF_HLO + boff);
        }
    }
    __syncthreads();
    grid_sync(jb, ++epoch);   // h0 conversion visible everywhere

    const int ub = tid >> 2, jjp = tid & 3;
    const int j0 = jb*8 + 2*jjp;
    float cs0 = 0.f, cs1 = 0.f;
    if (tid < 128) { cs0 = c0[ub*H_ + j0]; cs1 = c0[ub*H_ + j0 + 1]; }

    const int bl_r = lane & 7;
    const int bl_k = (lane >> 3) & 1;
    const size_t OFF_H = (size_t)B_*T_*H_;
    const size_t OFF_C = OFF_H + (size_t)B_*H_;

    // ===== Scan (round-14 structure, unchanged) =====
    for (int t = 0; t < T_; t++) {
        {
            const uint4* ph = (const uint4*)g_hh[t & 1];
            const uint4* pl = (const uint4*)g_hl[t & 1];
            #pragma unroll
            for (int it = 0; it < 4; it++) {
                int e = tid + NTHR*it;
                int b = e >> 7, kq = e & 127;
                *(uint4*)(sm + OFF_HHI + (b*HPITCH + kq*8)*2) = ph[e];
                *(uint4*)(sm + OFF_HLO + (b*HPITCH + kq*8)*2) = pl[e];
            }
            {
                int v = tid;
                int b = v >> 5, n = v & 31;
                int col = (n >> 3)*H_ + jb*8 + (n & 7);
                sxp[v] = g_xproj[((size_t)b*T_ + t)*G_ + col] + bhh[col];
            }
        }
        __syncthreads();

        {
            float acc[4][4];
            #pragma unroll
            for (int i = 0; i < 4; i++)
                acc[i][0]=acc[i][1]=acc[i][2]=acc[i][3]=0.f;
            #pragma unroll
            for (int kt = 0; kt < 4; kt++) {
                uint32_t k0 = (uint32_t)(ks*64 + kt*16 + bl_k*8);
                #pragma unroll
                for (int bt = 0; bt < 4; bt++) {
                    uint32_t bo = ((uint32_t)(bt*8 + bl_r)*HPITCH + k0)*2;
                    uint32_t bhi[2], blo[2];
                    ldsm_x2(bhi, smu + OFF_HHI + bo);
                    ldsm_x2(blo, smu + OFF_HLO + bo);
                    mma16816(acc[bt], aHi[kt], bhi);
                    mma16816(acc[bt], aHi[kt], blo);
                    mma16816(acc[bt], aLo[kt], bhi);
                }
            }
            int row = mt*16 + (lane >> 2);
            int bc  = (lane & 3)*2;
            #pragma unroll
            for (int bt = 0; bt < 4; bt++) {
                float* p0 = pd + (ks*32 + row)*36 + bt*8 + bc;
                p0[0] = acc[bt][0]; p0[1] = acc[bt][1];
                float* p1 = pd + (ks*32 + row + 8)*36 + bt*8 + bc;
                p1[0] = acc[bt][2]; p1[1] = acc[bt][3];
            }
        }
        __syncthreads();

        if (tid < 256) {
            int m = tid >> 3, q = tid & 7;
            float4 s = *(const float4*)(pd + m*36 + q*4);
            #pragma unroll
            for (int s16 = 1; s16 < 16; s16++) {
                float4 v = *(const float4*)(pd + (s16*32 + m)*36 + q*4);
                s.x += v.x; s.y += v.y; s.z += v.z; s.w += v.w;
            }
            *(float4*)(sp + m*40 + q*4) = s;
        }
        __syncthreads();

        if (tid < 128) {
            float pre0[4], pre1[4];
            #pragma unroll
            for (int g = 0; g < 4; g++) {
                int n0 = g*8 + 2*jjp;
                pre0[g] = sp[n0*40 + ub]     + sxp[ub*32 + n0];
                pre1[g] = sp[(n0+1)*40 + ub] + sxp[ub*32 + n0 + 1];
            }
            float i0 = 1.f/(1.f+__expf(-pre0[0]));
            float f0 = 1.f/(1.f+__expf(-pre0[1]));
            float o0 = 1.f/(1.f+__expf(-pre0[2]));
            float q0 = tanhf(pre0[3]);
            float i1 = 1.f/(1.f+__expf(-pre1[0]));
            float f1 = 1.f/(1.f+__expf(-pre1[1]));
            float o1 = 1.f/(1.f+__expf(-pre1[2]));
            float q1 = tanhf(pre1[3]);
            cs0 = cs0*f0 + i0*q0;
            cs1 = cs1*f1 + i1*q1;
            float hn0 = o0 * tanhf(cs0);
            float hn1 = o1 * tanhf(cs1);

            out[((size_t)ub*T_ + t)*H_ + j0]     = hn0;
            out[((size_t)ub*T_ + t)*H_ + j0 + 1] = hn1;
            if (t == T_ - 1) {
                out[OFF_H + (size_t)ub*H_ + j0]     = hn0;
                out[OFF_H + (size_t)ub*H_ + j0 + 1] = hn1;
                out[OFF_C + (size_t)ub*H_ + j0]     = cs0;
                out[OFF_C + (size_t)ub*H_ + j0 + 1] = cs1;
            }
            __nv_bfloat16 a0 = __float2bfloat16(hn0);
            __nv_bfloat16 a1 = __float2bfloat16(hn1);
            __nv_bfloat162 hp; hp.x = a0; hp.y = a1;
            __nv_bfloat162 lp;
            lp.x = __float2bfloat16(hn0 - __bfloat162float(a0));
            lp.y = __float2bfloat16(hn1 - __bfloat162float(a1));
            g_hh[(t+1)&1][ub*512 + jb*4 + jjp] = *(unsigned*)&hp;
            g_hl[(t+1)&1][ub*512 + jb*4 + jjp] = *(unsigned*)&lp;
        }

        if (t + 1 < T_) grid_sync(jb, ++epoch);
    }
}

extern "C" void kernel_launch(void* const* d_in, const int* in_sizes, int n_in,
                              void* d_out, int out_size)
{
    (void)in_sizes; (void)n_in; (void)out_size;
    const float* inputs = (const float*)d_in[0];
    const float* h0     = (const float*)d_in[1];
    const float* c0     = (const float*)d_in[2];
    const float* Wih    = (const float*)d_in[3];
    const float* bih    = (const float*)d_in[4];
    const float* Whh    = (const float*)d_in[5];
    const float* bhh    = (const float*)d_in[6];
    float* out = (float*)d_out;

    cudaFuncSetAttribute(lstm_fused,
                         cudaFuncAttributeMaxDynamicSharedMemorySize,
                         SMEM_BYTES);

    lstm_fused<<<NBLK, NTHR, SMEM_BYTES>>>(
        inputs, h0, c0, Wih, bih, Whh, bhh, out);
}